// round 15
// baseline (speedup 1.0000x reference)
#include <cuda_runtime.h>
#include <cuda_bf16.h>
#include <math.h>

// Problem constants
#define BATCH 2
#define SEQ 2048
#define DMODEL 1024
#define NHEADS 16
#define DK 64
#define MROWS (BATCH * SEQ)   // 4096

// Scratch buffers (device globals: no allocation allowed in kernel_launch)
__device__ float g_Q[MROWS * DMODEL];
__device__ float g_K[MROWS * DMODEL];
__device__ float g_V[MROWS * DMODEL];
__device__ float g_O[MROWS * DMODEL];
__device__ float2 g_rope[SEQ * 32];   // (cos, sin) per (s, pair-index)

// ----------------------------------------------------------------------------
// tf32 helpers
// ----------------------------------------------------------------------------
__device__ __forceinline__ unsigned tf32r(float f) {
    unsigned u;
    asm("cvt.rna.tf32.f32 %0, %1;" : "=r"(u) : "f"(f));
    return u;
}

__device__ __forceinline__ void mma_tf32(float& c0, float& c1, float& c2, float& c3,
                                         unsigned a0, unsigned a1, unsigned a2, unsigned a3,
                                         unsigned b0, unsigned b1) {
    asm volatile(
        "mma.sync.aligned.m16n8k8.row.col.f32.tf32.tf32.f32 "
        "{%0,%1,%2,%3}, {%4,%5,%6,%7}, {%8,%9}, {%0,%1,%2,%3};"
        : "+f"(c0), "+f"(c1), "+f"(c2), "+f"(c3)
        : "r"(a0), "r"(a1), "r"(a2), "r"(a3), "r"(b0), "r"(b1));
}

// ----------------------------------------------------------------------------
// GEMM (NT) via tf32 tensor-core mma: C[m,n] = sum_k A[m,k] * W[n,k]
// Tile 128x128, BK=16, 256 threads = 8 warps, warp tile 64x32 (2x4 warp grid).
// Operands tf32-rounded once at smem staging. Smem stride 20 words:
// fragment LDS pattern (20*g + t) mod 32 is a 32-permutation -> conflict-free.
// ----------------------------------------------------------------------------
#define BM 128
#define BN 128
#define GBK 16
#define SSTR 20   // smem row stride in words

__global__ void __launch_bounds__(256, 2) gemm_nt(const float* __restrict__ A,
                                                  const float* __restrict__ Wm,
                                                  float* __restrict__ C,
                                                  int M, int N, int K) {
    __shared__ unsigned As[BM * SSTR];   // [m-row][k] tf32 bits
    __shared__ unsigned Bs[BN * SSTR];   // [n-row][k] tf32 bits

    const int tid  = threadIdx.x;
    const int lane = tid & 31;
    const int wid  = tid >> 5;
    const int wm   = wid & 1;        // 0..1 -> 64-row m slab
    const int wn   = wid >> 1;       // 0..3 -> 32-col n slab
    const int g    = lane >> 2;      // fragment group 0..7
    const int t4   = lane & 3;       // fragment thread-in-group 0..3

    const int m0 = blockIdx.y * BM;
    const int n0 = blockIdx.x * BN;

    // staging map: 512 float4 per matrix per tile, 2 per thread
    const int lrow = tid >> 2;       // 0..63
    const int lc4  = tid & 3;        // 0..3 (float4 col)

    const float* aP0 = A  + (size_t)(m0 + lrow)      * K + lc4 * 4;
    const float* aP1 = A  + (size_t)(m0 + lrow + 64) * K + lc4 * 4;
    const float* bP0 = Wm + (size_t)(n0 + lrow)      * K + lc4 * 4;
    const float* bP1 = Wm + (size_t)(n0 + lrow + 64) * K + lc4 * 4;

    float acc[4][4][4];
#pragma unroll
    for (int i = 0; i < 4; i++)
#pragma unroll
        for (int j = 0; j < 4; j++)
#pragma unroll
            for (int r = 0; r < 4; r++) acc[i][j][r] = 0.f;

    float4 pa0 = *(const float4*)(aP0);
    float4 pa1 = *(const float4*)(aP1);
    float4 pb0 = *(const float4*)(bP0);
    float4 pb1 = *(const float4*)(bP1);

    const unsigned* Abase = As + (64 * wm) * SSTR;
    const unsigned* Bbase = Bs + (32 * wn) * SSTR;

    for (int k0 = 0; k0 < K; k0 += GBK) {
        // stage (with tf32 rounding)
        {
            unsigned* d;
            d = &As[lrow * SSTR + lc4 * 4];
            d[0] = tf32r(pa0.x); d[1] = tf32r(pa0.y); d[2] = tf32r(pa0.z); d[3] = tf32r(pa0.w);
            d = &As[(lrow + 64) * SSTR + lc4 * 4];
            d[0] = tf32r(pa1.x); d[1] = tf32r(pa1.y); d[2] = tf32r(pa1.z); d[3] = tf32r(pa1.w);
            d = &Bs[lrow * SSTR + lc4 * 4];
            d[0] = tf32r(pb0.x); d[1] = tf32r(pb0.y); d[2] = tf32r(pb0.z); d[3] = tf32r(pb0.w);
            d = &Bs[(lrow + 64) * SSTR + lc4 * 4];
            d[0] = tf32r(pb1.x); d[1] = tf32r(pb1.y); d[2] = tf32r(pb1.z); d[3] = tf32r(pb1.w);
        }
        __syncthreads();

        // prefetch next k-slab (latency hidden behind 32 MMAs)
        int kn = k0 + GBK;
        if (kn < K) {
            pa0 = *(const float4*)(aP0 + kn);
            pa1 = *(const float4*)(aP1 + kn);
            pb0 = *(const float4*)(bP0 + kn);
            pb1 = *(const float4*)(bP1 + kn);
        }

#pragma unroll
        for (int kk = 0; kk < GBK; kk += 8) {
            unsigned bf[4][2];
#pragma unroll
            for (int jn = 0; jn < 4; jn++) {
                const unsigned* bp = Bbase + (8 * jn + g) * SSTR + kk + t4;
                bf[jn][0] = bp[0];
                bf[jn][1] = bp[4];
            }
#pragma unroll
            for (int im = 0; im < 4; im++) {
                const unsigned* ap0 = Abase + (16 * im + g) * SSTR + kk + t4;
                const unsigned* ap1 = ap0 + 8 * SSTR;
                unsigned a0 = ap0[0], a1 = ap1[0], a2 = ap0[4], a3 = ap1[4];
#pragma unroll
                for (int jn = 0; jn < 4; jn++)
                    mma_tf32(acc[im][jn][0], acc[im][jn][1], acc[im][jn][2], acc[im][jn][3],
                             a0, a1, a2, a3, bf[jn][0], bf[jn][1]);
            }
        }
        __syncthreads();
    }

    // epilogue: c0,c1 -> (row, 2t..2t+1), c2,c3 -> (row+8, ...)
#pragma unroll
    for (int im = 0; im < 4; im++) {
        int row = m0 + 64 * wm + 16 * im + g;
#pragma unroll
        for (int jn = 0; jn < 4; jn++) {
            int col = n0 + 32 * wn + 8 * jn + 2 * t4;
            *(float2*)&C[(size_t)row * N + col]       = make_float2(acc[im][jn][0], acc[im][jn][1]);
            *(float2*)&C[(size_t)(row + 8) * N + col] = make_float2(acc[im][jn][2], acc[im][jn][3]);
        }
    }
}

// ----------------------------------------------------------------------------
// RoPE stage 1: build (cos, sin) table with double math (65536 threads only).
// ----------------------------------------------------------------------------
__global__ void rope_tables(const int* __restrict__ tp) {
    int idx = blockIdx.x * blockDim.x + threadIdx.x;   // over SEQ*32
    if (idx >= SEQ * 32) return;
    int s = idx >> 5;
    int i = idx & 31;
    double pos  = (double)tp[s];
    double freq = exp(-((double)(2 * i) / 64.0) * 9.210340371976184);
    double ang  = pos * freq;
    g_rope[idx] = make_float2((float)cos(ang), (float)sin(ang));
}

// ----------------------------------------------------------------------------
// RoPE stage 2: pure fp32 apply, float2-coalesced, memory-bound.
// ----------------------------------------------------------------------------
__global__ void rope_apply(float2* __restrict__ Qb, float2* __restrict__ Kb) {
    int idx = blockIdx.x * blockDim.x + threadIdx.x;   // over B*S*(D/2)
    if (idx >= BATCH * SEQ * (DMODEL / 2)) return;
    int d2 = idx & (DMODEL / 2 - 1);
    int bs = idx >> 9;
    int s  = bs & (SEQ - 1);
    int i  = d2 & 31;

    float2 cs = g_rope[(s << 5) | i];

    float2 q = Qb[idx];
    Qb[idx] = make_float2(q.x * cs.x - q.y * cs.y, q.x * cs.y + q.y * cs.x);
    float2 k = Kb[idx];
    Kb[idx] = make_float2(k.x * cs.x - k.y * cs.y, k.x * cs.y + k.y * cs.x);
}

// ----------------------------------------------------------------------------
// Causal flash attention (fp32 SIMT). One block = one (b, h, 64-row q tile).
// qt reversed: longest blocks (most k-tiles) launch first -> smaller tail.
// ----------------------------------------------------------------------------
__global__ void __launch_bounds__(64) attn_kernel(const float* __restrict__ Q,
                                                  const float* __restrict__ K,
                                                  const float* __restrict__ V,
                                                  float* __restrict__ O) {
    __shared__ float Ks[64 * 64];
    __shared__ float Vs[64 * 64];
    __shared__ float scr[64 * 64];   // scr[k*64 + t]: bank = lane, conflict-free

    const int t  = threadIdx.x;
    const int qt = (int)gridDim.x - 1 - (int)blockIdx.x;   // longest first
    const int h  = blockIdx.y;
    const int b  = blockIdx.z;
    const int q0 = qt * 64;

    const float* qptr = Q + ((size_t)(b * SEQ + q0 + t)) * DMODEL + h * DK;
    float q[DK];
#pragma unroll
    for (int d = 0; d < DK; d += 4) {
        float4 v4 = *(const float4*)(qptr + d);
        q[d] = v4.x; q[d + 1] = v4.y; q[d + 2] = v4.z; q[d + 3] = v4.w;
    }
    float o[DK];
#pragma unroll
    for (int d = 0; d < DK; d++) o[d] = 0.f;
    float m = -1e30f, l = 0.f;

    for (int kt = 0; kt <= qt; kt++) {
        const float* kbase = K + ((size_t)(b * SEQ + kt * 64)) * DMODEL + h * DK;
        const float* vbase = V + ((size_t)(b * SEQ + kt * 64)) * DMODEL + h * DK;
#pragma unroll
        for (int it = 0; it < 16; it++) {
            int flat4 = it * 64 + t;
            int kr = flat4 >> 4;
            int d4 = (flat4 & 15) * 4;
            *(float4*)&Ks[kr * 64 + d4] = *(const float4*)(kbase + (size_t)kr * DMODEL + d4);
            *(float4*)&Vs[kr * 64 + d4] = *(const float4*)(vbase + (size_t)kr * DMODEL + d4);
        }
        __syncthreads();

        const int kmax = (kt == qt) ? (t + 1) : 64;   // causal

        float tm = -1e30f;
        for (int k = 0; k < kmax; k++) {
            float s = 0.f;
#pragma unroll
            for (int d = 0; d < DK; d += 4) {
                float4 kv = *(const float4*)&Ks[k * 64 + d];
                s += q[d] * kv.x + q[d + 1] * kv.y + q[d + 2] * kv.z + q[d + 3] * kv.w;
            }
            s *= 0.125f;   // 1/sqrt(64)
            scr[k * 64 + t] = s;
            tm = fmaxf(tm, s);
        }

        float mn   = fmaxf(m, tm);
        float corr = __expf(m - mn);
        float lsum = 0.f;
        for (int k = 0; k < kmax; k++) {
            float p = __expf(scr[k * 64 + t] - mn);
            scr[k * 64 + t] = p;
            lsum += p;
        }
        l = l * corr + lsum;
#pragma unroll
        for (int d = 0; d < DK; d++) o[d] *= corr;

        for (int k = 0; k < kmax; k++) {
            float p = scr[k * 64 + t];
#pragma unroll
            for (int d = 0; d < DK; d += 4) {
                float4 vv = *(const float4*)&Vs[k * 64 + d];
                o[d]     += p * vv.x;
                o[d + 1] += p * vv.y;
                o[d + 2] += p * vv.z;
                o[d + 3] += p * vv.w;
            }
        }
        m = mn;
        __syncthreads();
    }

    float inv = 1.f / l;
    float* optr = O + ((size_t)(b * SEQ + q0 + t)) * DMODEL + h * DK;
#pragma unroll
    for (int d = 0; d < DK; d += 4) {
        float4 v4 = make_float4(o[d] * inv, o[d + 1] * inv, o[d + 2] * inv, o[d + 3] * inv);
        *(float4*)(optr + d) = v4;
    }
}

// ----------------------------------------------------------------------------
// Launch
// ----------------------------------------------------------------------------
extern "C" void kernel_launch(void* const* d_in, const int* in_sizes, int n_in,
                              void* d_out, int out_size) {
    (void)in_sizes; (void)n_in; (void)out_size;
    const float* x  = (const float*)d_in[0];
    const int*   tp = (const int*)d_in[1];
    const float* Wq = (const float*)d_in[2];
    const float* Wk = (const float*)d_in[3];
    const float* Wv = (const float*)d_in[4];
    const float* Wo = (const float*)d_in[5];
    float* out = (float*)d_out;

    float *Qp, *Kp, *Vp, *Op;
    cudaGetSymbolAddress((void**)&Qp, g_Q);
    cudaGetSymbolAddress((void**)&Kp, g_K);
    cudaGetSymbolAddress((void**)&Vp, g_V);
    cudaGetSymbolAddress((void**)&Op, g_O);

    dim3 gg(DMODEL / BN, MROWS / BM);   // (8, 32)
    gemm_nt<<<gg, 256>>>(x, Wq, Qp, MROWS, DMODEL, DMODEL);
    gemm_nt<<<gg, 256>>>(x, Wk, Kp, MROWS, DMODEL, DMODEL);
    gemm_nt<<<gg, 256>>>(x, Wv, Vp, MROWS, DMODEL, DMODEL);

    rope_tables<<<(SEQ * 32 + 255) / 256, 256>>>(tp);
    int ropeN = BATCH * SEQ * (DMODEL / 2);
    rope_apply<<<(ropeN + 255) / 256, 256>>>((float2*)Qp, (float2*)Kp);

    attn_kernel<<<dim3(SEQ / 64, NHEADS, BATCH), 64>>>(Qp, Kp, Vp, Op);

    gemm_nt<<<gg, 256>>>(Op, Wo, out, MROWS, DMODEL, DMODEL);
}

// round 16
// speedup vs baseline: 1.0003x; 1.0003x over previous
#include <cuda_runtime.h>
#include <cuda_bf16.h>
#include <math.h>

// Problem constants
#define BATCH 2
#define SEQ 2048
#define DMODEL 1024
#define NHEADS 16
#define DK 64
#define MROWS (BATCH * SEQ)   // 4096

// Scratch buffers (device globals: no allocation allowed in kernel_launch)
__device__ float g_Q[MROWS * DMODEL];
__device__ float g_K[MROWS * DMODEL];
__device__ float g_V[MROWS * DMODEL];
__device__ float g_O[MROWS * DMODEL];
__device__ float2 g_rope[SEQ * 32];   // (cos, sin) per (s, pair-index)

// ----------------------------------------------------------------------------
// tf32 helpers
// ----------------------------------------------------------------------------
__device__ __forceinline__ unsigned tf32r(float f) {
    unsigned u;
    asm("cvt.rna.tf32.f32 %0, %1;" : "=r"(u) : "f"(f));
    return u;
}

__device__ __forceinline__ void mma_tf32(float& c0, float& c1, float& c2, float& c3,
                                         unsigned a0, unsigned a1, unsigned a2, unsigned a3,
                                         unsigned b0, unsigned b1) {
    asm volatile(
        "mma.sync.aligned.m16n8k8.row.col.f32.tf32.tf32.f32 "
        "{%0,%1,%2,%3}, {%4,%5,%6,%7}, {%8,%9}, {%0,%1,%2,%3};"
        : "+f"(c0), "+f"(c1), "+f"(c2), "+f"(c3)
        : "r"(a0), "r"(a1), "r"(a2), "r"(a3), "r"(b0), "r"(b1));
}

// ----------------------------------------------------------------------------
// GEMM (NT) via tf32 tensor-core mma: C[m,n] = sum_k A[m,k] * W[n,k]
// Tile 128x128, BK=16, 256 threads = 8 warps, warp tile 64x32 (2x4 warp grid).
// Operands tf32-rounded once at smem staging. Smem stride 20 words:
// fragment LDS pattern (20*g + t) mod 32 is a 32-permutation -> conflict-free.
// ----------------------------------------------------------------------------
#define BM 128
#define BN 128
#define GBK 16
#define SSTR 20   // smem row stride in words

__global__ void __launch_bounds__(256, 2) gemm_nt(const float* __restrict__ A,
                                                  const float* __restrict__ Wm,
                                                  float* __restrict__ C,
                                                  int M, int N, int K) {
    __shared__ unsigned As[BM * SSTR];   // [m-row][k] tf32 bits
    __shared__ unsigned Bs[BN * SSTR];   // [n-row][k] tf32 bits

    const int tid  = threadIdx.x;
    const int lane = tid & 31;
    const int wid  = tid >> 5;
    const int wm   = wid & 1;        // 0..1 -> 64-row m slab
    const int wn   = wid >> 1;       // 0..3 -> 32-col n slab
    const int g    = lane >> 2;      // fragment group 0..7
    const int t4   = lane & 3;       // fragment thread-in-group 0..3

    const int m0 = blockIdx.y * BM;
    const int n0 = blockIdx.x * BN;

    // staging map: 512 float4 per matrix per tile, 2 per thread
    const int lrow = tid >> 2;       // 0..63
    const int lc4  = tid & 3;        // 0..3 (float4 col)

    const float* aP0 = A  + (size_t)(m0 + lrow)      * K + lc4 * 4;
    const float* aP1 = A  + (size_t)(m0 + lrow + 64) * K + lc4 * 4;
    const float* bP0 = Wm + (size_t)(n0 + lrow)      * K + lc4 * 4;
    const float* bP1 = Wm + (size_t)(n0 + lrow + 64) * K + lc4 * 4;

    float acc[4][4][4];
#pragma unroll
    for (int i = 0; i < 4; i++)
#pragma unroll
        for (int j = 0; j < 4; j++)
#pragma unroll
            for (int r = 0; r < 4; r++) acc[i][j][r] = 0.f;

    float4 pa0 = *(const float4*)(aP0);
    float4 pa1 = *(const float4*)(aP1);
    float4 pb0 = *(const float4*)(bP0);
    float4 pb1 = *(const float4*)(bP1);

    const unsigned* Abase = As + (64 * wm) * SSTR;
    const unsigned* Bbase = Bs + (32 * wn) * SSTR;

    for (int k0 = 0; k0 < K; k0 += GBK) {
        // stage (with tf32 rounding)
        {
            unsigned* d;
            d = &As[lrow * SSTR + lc4 * 4];
            d[0] = tf32r(pa0.x); d[1] = tf32r(pa0.y); d[2] = tf32r(pa0.z); d[3] = tf32r(pa0.w);
            d = &As[(lrow + 64) * SSTR + lc4 * 4];
            d[0] = tf32r(pa1.x); d[1] = tf32r(pa1.y); d[2] = tf32r(pa1.z); d[3] = tf32r(pa1.w);
            d = &Bs[lrow * SSTR + lc4 * 4];
            d[0] = tf32r(pb0.x); d[1] = tf32r(pb0.y); d[2] = tf32r(pb0.z); d[3] = tf32r(pb0.w);
            d = &Bs[(lrow + 64) * SSTR + lc4 * 4];
            d[0] = tf32r(pb1.x); d[1] = tf32r(pb1.y); d[2] = tf32r(pb1.z); d[3] = tf32r(pb1.w);
        }
        __syncthreads();

        // prefetch next k-slab (latency hidden behind 32 MMAs)
        int kn = k0 + GBK;
        if (kn < K) {
            pa0 = *(const float4*)(aP0 + kn);
            pa1 = *(const float4*)(aP1 + kn);
            pb0 = *(const float4*)(bP0 + kn);
            pb1 = *(const float4*)(bP1 + kn);
        }

#pragma unroll
        for (int kk = 0; kk < GBK; kk += 8) {
            unsigned bf[4][2];
#pragma unroll
            for (int jn = 0; jn < 4; jn++) {
                const unsigned* bp = Bbase + (8 * jn + g) * SSTR + kk + t4;
                bf[jn][0] = bp[0];
                bf[jn][1] = bp[4];
            }
#pragma unroll
            for (int im = 0; im < 4; im++) {
                const unsigned* ap0 = Abase + (16 * im + g) * SSTR + kk + t4;
                const unsigned* ap1 = ap0 + 8 * SSTR;
                unsigned a0 = ap0[0], a1 = ap1[0], a2 = ap0[4], a3 = ap1[4];
#pragma unroll
                for (int jn = 0; jn < 4; jn++)
                    mma_tf32(acc[im][jn][0], acc[im][jn][1], acc[im][jn][2], acc[im][jn][3],
                             a0, a1, a2, a3, bf[jn][0], bf[jn][1]);
            }
        }
        __syncthreads();
    }

    // epilogue: c0,c1 -> (row, 2t..2t+1), c2,c3 -> (row+8, ...)
#pragma unroll
    for (int im = 0; im < 4; im++) {
        int row = m0 + 64 * wm + 16 * im + g;
#pragma unroll
        for (int jn = 0; jn < 4; jn++) {
            int col = n0 + 32 * wn + 8 * jn + 2 * t4;
            *(float2*)&C[(size_t)row * N + col]       = make_float2(acc[im][jn][0], acc[im][jn][1]);
            *(float2*)&C[(size_t)(row + 8) * N + col] = make_float2(acc[im][jn][2], acc[im][jn][3]);
        }
    }
}

// ----------------------------------------------------------------------------
// RoPE stage 1: build (cos, sin) table with double math (65536 threads only).
// ----------------------------------------------------------------------------
__global__ void rope_tables(const int* __restrict__ tp) {
    int idx = blockIdx.x * blockDim.x + threadIdx.x;   // over SEQ*32
    if (idx >= SEQ * 32) return;
    int s = idx >> 5;
    int i = idx & 31;
    double pos  = (double)tp[s];
    double freq = exp(-((double)(2 * i) / 64.0) * 9.210340371976184);
    double ang  = pos * freq;
    g_rope[idx] = make_float2((float)cos(ang), (float)sin(ang));
}

// ----------------------------------------------------------------------------
// RoPE stage 2: pure fp32 apply, float2-coalesced, memory-bound.
// ----------------------------------------------------------------------------
__global__ void rope_apply(float2* __restrict__ Qb, float2* __restrict__ Kb) {
    int idx = blockIdx.x * blockDim.x + threadIdx.x;   // over B*S*(D/2)
    if (idx >= BATCH * SEQ * (DMODEL / 2)) return;
    int d2 = idx & (DMODEL / 2 - 1);
    int bs = idx >> 9;
    int s  = bs & (SEQ - 1);
    int i  = d2 & 31;

    float2 cs = g_rope[(s << 5) | i];

    float2 q = Qb[idx];
    Qb[idx] = make_float2(q.x * cs.x - q.y * cs.y, q.x * cs.y + q.y * cs.x);
    float2 k = Kb[idx];
    Kb[idx] = make_float2(k.x * cs.x - k.y * cs.y, k.x * cs.y + k.y * cs.x);
}

// ----------------------------------------------------------------------------
// Causal flash attention (fp32 SIMT). One block = one (b, h, 64-row q tile).
// qt reversed: longest blocks (most k-tiles) launch first -> smaller tail.
// ----------------------------------------------------------------------------
__global__ void __launch_bounds__(64) attn_kernel(const float* __restrict__ Q,
                                                  const float* __restrict__ K,
                                                  const float* __restrict__ V,
                                                  float* __restrict__ O) {
    __shared__ float Ks[64 * 64];
    __shared__ float Vs[64 * 64];
    __shared__ float scr[64 * 64];   // scr[k*64 + t]: bank = lane, conflict-free

    const int t  = threadIdx.x;
    const int qt = (int)gridDim.x - 1 - (int)blockIdx.x;   // longest first
    const int h  = blockIdx.y;
    const int b  = blockIdx.z;
    const int q0 = qt * 64;

    const float* qptr = Q + ((size_t)(b * SEQ + q0 + t)) * DMODEL + h * DK;
    float q[DK];
#pragma unroll
    for (int d = 0; d < DK; d += 4) {
        float4 v4 = *(const float4*)(qptr + d);
        q[d] = v4.x; q[d + 1] = v4.y; q[d + 2] = v4.z; q[d + 3] = v4.w;
    }
    float o[DK];
#pragma unroll
    for (int d = 0; d < DK; d++) o[d] = 0.f;
    float m = -1e30f, l = 0.f;

    for (int kt = 0; kt <= qt; kt++) {
        const float* kbase = K + ((size_t)(b * SEQ + kt * 64)) * DMODEL + h * DK;
        const float* vbase = V + ((size_t)(b * SEQ + kt * 64)) * DMODEL + h * DK;
#pragma unroll
        for (int it = 0; it < 16; it++) {
            int flat4 = it * 64 + t;
            int kr = flat4 >> 4;
            int d4 = (flat4 & 15) * 4;
            *(float4*)&Ks[kr * 64 + d4] = *(const float4*)(kbase + (size_t)kr * DMODEL + d4);
            *(float4*)&Vs[kr * 64 + d4] = *(const float4*)(vbase + (size_t)kr * DMODEL + d4);
        }
        __syncthreads();

        const int kmax = (kt == qt) ? (t + 1) : 64;   // causal

        float tm = -1e30f;
        for (int k = 0; k < kmax; k++) {
            float s = 0.f;
#pragma unroll
            for (int d = 0; d < DK; d += 4) {
                float4 kv = *(const float4*)&Ks[k * 64 + d];
                s += q[d] * kv.x + q[d + 1] * kv.y + q[d + 2] * kv.z + q[d + 3] * kv.w;
            }
            s *= 0.125f;   // 1/sqrt(64)
            scr[k * 64 + t] = s;
            tm = fmaxf(tm, s);
        }

        float mn   = fmaxf(m, tm);
        float corr = __expf(m - mn);
        float lsum = 0.f;
        for (int k = 0; k < kmax; k++) {
            float p = __expf(scr[k * 64 + t] - mn);
            scr[k * 64 + t] = p;
            lsum += p;
        }
        l = l * corr + lsum;
#pragma unroll
        for (int d = 0; d < DK; d++) o[d] *= corr;

        for (int k = 0; k < kmax; k++) {
            float p = scr[k * 64 + t];
#pragma unroll
            for (int d = 0; d < DK; d += 4) {
                float4 vv = *(const float4*)&Vs[k * 64 + d];
                o[d]     += p * vv.x;
                o[d + 1] += p * vv.y;
                o[d + 2] += p * vv.z;
                o[d + 3] += p * vv.w;
            }
        }
        m = mn;
        __syncthreads();
    }

    float inv = 1.f / l;
    float* optr = O + ((size_t)(b * SEQ + q0 + t)) * DMODEL + h * DK;
#pragma unroll
    for (int d = 0; d < DK; d += 4) {
        float4 v4 = make_float4(o[d] * inv, o[d + 1] * inv, o[d + 2] * inv, o[d + 3] * inv);
        *(float4*)(optr + d) = v4;
    }
}

// ----------------------------------------------------------------------------
// Launch
// ----------------------------------------------------------------------------
extern "C" void kernel_launch(void* const* d_in, const int* in_sizes, int n_in,
                              void* d_out, int out_size) {
    (void)in_sizes; (void)n_in; (void)out_size;
    const float* x  = (const float*)d_in[0];
    const int*   tp = (const int*)d_in[1];
    const float* Wq = (const float*)d_in[2];
    const float* Wk = (const float*)d_in[3];
    const float* Wv = (const float*)d_in[4];
    const float* Wo = (const float*)d_in[5];
    float* out = (float*)d_out;

    float *Qp, *Kp, *Vp, *Op;
    cudaGetSymbolAddress((void**)&Qp, g_Q);
    cudaGetSymbolAddress((void**)&Kp, g_K);
    cudaGetSymbolAddress((void**)&Vp, g_V);
    cudaGetSymbolAddress((void**)&Op, g_O);

    dim3 gg(DMODEL / BN, MROWS / BM);   // (8, 32)
    gemm_nt<<<gg, 256>>>(x, Wq, Qp, MROWS, DMODEL, DMODEL);
    gemm_nt<<<gg, 256>>>(x, Wk, Kp, MROWS, DMODEL, DMODEL);
    gemm_nt<<<gg, 256>>>(x, Wv, Vp, MROWS, DMODEL, DMODEL);

    rope_tables<<<(SEQ * 32 + 255) / 256, 256>>>(tp);
    int ropeN = BATCH * SEQ * (DMODEL / 2);
    rope_apply<<<(ropeN + 255) / 256, 256>>>((float2*)Qp, (float2*)Kp);

    attn_kernel<<<dim3(SEQ / 64, NHEADS, BATCH), 64>>>(Qp, Kp, Vp, Op);

    gemm_nt<<<gg, 256>>>(Op, Wo, out, MROWS, DMODEL, DMODEL);
}

// round 17
// speedup vs baseline: 1.0089x; 1.0086x over previous
#include <cuda_runtime.h>
#include <cuda_bf16.h>
#include <math.h>

// Problem constants
#define BATCH 2
#define SEQ 2048
#define DMODEL 1024
#define NHEADS 16
#define DK 64
#define MROWS (BATCH * SEQ)   // 4096

// Scratch buffers (device globals: no allocation allowed in kernel_launch)
__device__ float g_Q[MROWS * DMODEL];
__device__ float g_K[MROWS * DMODEL];
__device__ float g_V[MROWS * DMODEL];
__device__ float g_O[MROWS * DMODEL];
__device__ float2 g_rope[SEQ * 32];   // (cos, sin) per (s, pair-index)

// ----------------------------------------------------------------------------
// tf32 helpers
// ----------------------------------------------------------------------------
__device__ __forceinline__ unsigned tf32r(float f) {
    unsigned u;
    asm("cvt.rna.tf32.f32 %0, %1;" : "=r"(u) : "f"(f));
    return u;
}

__device__ __forceinline__ void mma_tf32(float& c0, float& c1, float& c2, float& c3,
                                         unsigned a0, unsigned a1, unsigned a2, unsigned a3,
                                         unsigned b0, unsigned b1) {
    asm volatile(
        "mma.sync.aligned.m16n8k8.row.col.f32.tf32.tf32.f32 "
        "{%0,%1,%2,%3}, {%4,%5,%6,%7}, {%8,%9}, {%0,%1,%2,%3};"
        : "+f"(c0), "+f"(c1), "+f"(c2), "+f"(c3)
        : "r"(a0), "r"(a1), "r"(a2), "r"(a3), "r"(b0), "r"(b1));
}

// ----------------------------------------------------------------------------
// GEMM (NT) via tf32 tensor-core mma: C[m,n] = sum_k A[m,k] * W[n,k]
// Tile 128x128, BK=16, 256 threads = 8 warps, warp tile 64x32 (2x4 warp grid).
// Operands tf32-rounded once at smem staging. Smem stride 20 words:
// fragment LDS pattern (20*g + t) mod 32 is a 32-permutation -> conflict-free.
// ----------------------------------------------------------------------------
#define BM 128
#define BN 128
#define GBK 16
#define SSTR 20   // smem row stride in words

__global__ void __launch_bounds__(256, 2) gemm_nt(const float* __restrict__ A,
                                                  const float* __restrict__ Wm,
                                                  float* __restrict__ C,
                                                  int M, int N, int K) {
    __shared__ unsigned As[BM * SSTR];   // [m-row][k] tf32 bits
    __shared__ unsigned Bs[BN * SSTR];   // [n-row][k] tf32 bits

    const int tid  = threadIdx.x;
    const int lane = tid & 31;
    const int wid  = tid >> 5;
    const int wm   = wid & 1;        // 0..1 -> 64-row m slab
    const int wn   = wid >> 1;       // 0..3 -> 32-col n slab
    const int g    = lane >> 2;      // fragment group 0..7
    const int t4   = lane & 3;       // fragment thread-in-group 0..3

    const int m0 = blockIdx.y * BM;
    const int n0 = blockIdx.x * BN;

    // staging map: 512 float4 per matrix per tile, 2 per thread
    const int lrow = tid >> 2;       // 0..63
    const int lc4  = tid & 3;        // 0..3 (float4 col)

    const float* aP0 = A  + (size_t)(m0 + lrow)      * K + lc4 * 4;
    const float* aP1 = A  + (size_t)(m0 + lrow + 64) * K + lc4 * 4;
    const float* bP0 = Wm + (size_t)(n0 + lrow)      * K + lc4 * 4;
    const float* bP1 = Wm + (size_t)(n0 + lrow + 64) * K + lc4 * 4;

    float acc[4][4][4];
#pragma unroll
    for (int i = 0; i < 4; i++)
#pragma unroll
        for (int j = 0; j < 4; j++)
#pragma unroll
            for (int r = 0; r < 4; r++) acc[i][j][r] = 0.f;

    float4 pa0 = *(const float4*)(aP0);
    float4 pa1 = *(const float4*)(aP1);
    float4 pb0 = *(const float4*)(bP0);
    float4 pb1 = *(const float4*)(bP1);

    const unsigned* Abase = As + (64 * wm) * SSTR;
    const unsigned* Bbase = Bs + (32 * wn) * SSTR;

    for (int k0 = 0; k0 < K; k0 += GBK) {
        // stage (with tf32 rounding)
        {
            unsigned* d;
            d = &As[lrow * SSTR + lc4 * 4];
            d[0] = tf32r(pa0.x); d[1] = tf32r(pa0.y); d[2] = tf32r(pa0.z); d[3] = tf32r(pa0.w);
            d = &As[(lrow + 64) * SSTR + lc4 * 4];
            d[0] = tf32r(pa1.x); d[1] = tf32r(pa1.y); d[2] = tf32r(pa1.z); d[3] = tf32r(pa1.w);
            d = &Bs[lrow * SSTR + lc4 * 4];
            d[0] = tf32r(pb0.x); d[1] = tf32r(pb0.y); d[2] = tf32r(pb0.z); d[3] = tf32r(pb0.w);
            d = &Bs[(lrow + 64) * SSTR + lc4 * 4];
            d[0] = tf32r(pb1.x); d[1] = tf32r(pb1.y); d[2] = tf32r(pb1.z); d[3] = tf32r(pb1.w);
        }
        __syncthreads();

        // prefetch next k-slab (latency hidden behind 32 MMAs)
        int kn = k0 + GBK;
        if (kn < K) {
            pa0 = *(const float4*)(aP0 + kn);
            pa1 = *(const float4*)(aP1 + kn);
            pb0 = *(const float4*)(bP0 + kn);
            pb1 = *(const float4*)(bP1 + kn);
        }

#pragma unroll
        for (int kk = 0; kk < GBK; kk += 8) {
            unsigned bf[4][2];
#pragma unroll
            for (int jn = 0; jn < 4; jn++) {
                const unsigned* bp = Bbase + (8 * jn + g) * SSTR + kk + t4;
                bf[jn][0] = bp[0];
                bf[jn][1] = bp[4];
            }
#pragma unroll
            for (int im = 0; im < 4; im++) {
                const unsigned* ap0 = Abase + (16 * im + g) * SSTR + kk + t4;
                const unsigned* ap1 = ap0 + 8 * SSTR;
                unsigned a0 = ap0[0], a1 = ap1[0], a2 = ap0[4], a3 = ap1[4];
#pragma unroll
                for (int jn = 0; jn < 4; jn++)
                    mma_tf32(acc[im][jn][0], acc[im][jn][1], acc[im][jn][2], acc[im][jn][3],
                             a0, a1, a2, a3, bf[jn][0], bf[jn][1]);
            }
        }
        __syncthreads();
    }

    // epilogue: c0,c1 -> (row, 2t..2t+1), c2,c3 -> (row+8, ...)
#pragma unroll
    for (int im = 0; im < 4; im++) {
        int row = m0 + 64 * wm + 16 * im + g;
#pragma unroll
        for (int jn = 0; jn < 4; jn++) {
            int col = n0 + 32 * wn + 8 * jn + 2 * t4;
            *(float2*)&C[(size_t)row * N + col]       = make_float2(acc[im][jn][0], acc[im][jn][1]);
            *(float2*)&C[(size_t)(row + 8) * N + col] = make_float2(acc[im][jn][2], acc[im][jn][3]);
        }
    }
}

// ----------------------------------------------------------------------------
// RoPE stage 1: build (cos, sin) table with double math (65536 threads only).
// ----------------------------------------------------------------------------
__global__ void rope_tables(const int* __restrict__ tp) {
    int idx = blockIdx.x * blockDim.x + threadIdx.x;   // over SEQ*32
    if (idx >= SEQ * 32) return;
    int s = idx >> 5;
    int i = idx & 31;
    double pos  = (double)tp[s];
    double freq = exp(-((double)(2 * i) / 64.0) * 9.210340371976184);
    double ang  = pos * freq;
    g_rope[idx] = make_float2((float)cos(ang), (float)sin(ang));
}

// ----------------------------------------------------------------------------
// RoPE stage 2: pure fp32 apply, float2-coalesced, memory-bound.
// ----------------------------------------------------------------------------
__global__ void rope_apply(float2* __restrict__ Qb, float2* __restrict__ Kb) {
    int idx = blockIdx.x * blockDim.x + threadIdx.x;   // over B*S*(D/2)
    if (idx >= BATCH * SEQ * (DMODEL / 2)) return;
    int d2 = idx & (DMODEL / 2 - 1);
    int bs = idx >> 9;
    int s  = bs & (SEQ - 1);
    int i  = d2 & 31;

    float2 cs = g_rope[(s << 5) | i];

    float2 q = Qb[idx];
    Qb[idx] = make_float2(q.x * cs.x - q.y * cs.y, q.x * cs.y + q.y * cs.x);
    float2 k = Kb[idx];
    Kb[idx] = make_float2(k.x * cs.x - k.y * cs.y, k.x * cs.y + k.y * cs.x);
}

// ----------------------------------------------------------------------------
// Causal flash attention (fp32 SIMT). One block = one (b, h, 64-row q tile).
// qt reversed: longest blocks (most k-tiles) launch first -> smaller tail.
// ----------------------------------------------------------------------------
__global__ void __launch_bounds__(64) attn_kernel(const float* __restrict__ Q,
                                                  const float* __restrict__ K,
                                                  const float* __restrict__ V,
                                                  float* __restrict__ O) {
    __shared__ float Ks[64 * 64];
    __shared__ float Vs[64 * 64];
    __shared__ float scr[64 * 64];   // scr[k*64 + t]: bank = lane, conflict-free

    const int t  = threadIdx.x;
    const int qt = (int)gridDim.x - 1 - (int)blockIdx.x;   // longest first
    const int h  = blockIdx.y;
    const int b  = blockIdx.z;
    const int q0 = qt * 64;

    const float* qptr = Q + ((size_t)(b * SEQ + q0 + t)) * DMODEL + h * DK;
    float q[DK];
#pragma unroll
    for (int d = 0; d < DK; d += 4) {
        float4 v4 = *(const float4*)(qptr + d);
        q[d] = v4.x; q[d + 1] = v4.y; q[d + 2] = v4.z; q[d + 3] = v4.w;
    }
    float o[DK];
#pragma unroll
    for (int d = 0; d < DK; d++) o[d] = 0.f;
    float m = -1e30f, l = 0.f;

    for (int kt = 0; kt <= qt; kt++) {
        const float* kbase = K + ((size_t)(b * SEQ + kt * 64)) * DMODEL + h * DK;
        const float* vbase = V + ((size_t)(b * SEQ + kt * 64)) * DMODEL + h * DK;
#pragma unroll
        for (int it = 0; it < 16; it++) {
            int flat4 = it * 64 + t;
            int kr = flat4 >> 4;
            int d4 = (flat4 & 15) * 4;
            *(float4*)&Ks[kr * 64 + d4] = *(const float4*)(kbase + (size_t)kr * DMODEL + d4);
            *(float4*)&Vs[kr * 64 + d4] = *(const float4*)(vbase + (size_t)kr * DMODEL + d4);
        }
        __syncthreads();

        const int kmax = (kt == qt) ? (t + 1) : 64;   // causal

        float tm = -1e30f;
        for (int k = 0; k < kmax; k++) {
            float s = 0.f;
#pragma unroll
            for (int d = 0; d < DK; d += 4) {
                float4 kv = *(const float4*)&Ks[k * 64 + d];
                s += q[d] * kv.x + q[d + 1] * kv.y + q[d + 2] * kv.z + q[d + 3] * kv.w;
            }
            s *= 0.125f;   // 1/sqrt(64)
            scr[k * 64 + t] = s;
            tm = fmaxf(tm, s);
        }

        float mn   = fmaxf(m, tm);
        float corr = __expf(m - mn);
        float lsum = 0.f;
        for (int k = 0; k < kmax; k++) {
            float p = __expf(scr[k * 64 + t] - mn);
            scr[k * 64 + t] = p;
            lsum += p;
        }
        l = l * corr + lsum;
#pragma unroll
        for (int d = 0; d < DK; d++) o[d] *= corr;

        for (int k = 0; k < kmax; k++) {
            float p = scr[k * 64 + t];
#pragma unroll
            for (int d = 0; d < DK; d += 4) {
                float4 vv = *(const float4*)&Vs[k * 64 + d];
                o[d]     += p * vv.x;
                o[d + 1] += p * vv.y;
                o[d + 2] += p * vv.z;
                o[d + 3] += p * vv.w;
            }
        }
        m = mn;
        __syncthreads();
    }

    float inv = 1.f / l;
    float* optr = O + ((size_t)(b * SEQ + q0 + t)) * DMODEL + h * DK;
#pragma unroll
    for (int d = 0; d < DK; d += 4) {
        float4 v4 = make_float4(o[d] * inv, o[d + 1] * inv, o[d + 2] * inv, o[d + 3] * inv);
        *(float4*)(optr + d) = v4;
    }
}

// ----------------------------------------------------------------------------
// Launch
// ----------------------------------------------------------------------------
extern "C" void kernel_launch(void* const* d_in, const int* in_sizes, int n_in,
                              void* d_out, int out_size) {
    (void)in_sizes; (void)n_in; (void)out_size;
    const float* x  = (const float*)d_in[0];
    const int*   tp = (const int*)d_in[1];
    const float* Wq = (const float*)d_in[2];
    const float* Wk = (const float*)d_in[3];
    const float* Wv = (const float*)d_in[4];
    const float* Wo = (const float*)d_in[5];
    float* out = (float*)d_out;

    float *Qp, *Kp, *Vp, *Op;
    cudaGetSymbolAddress((void**)&Qp, g_Q);
    cudaGetSymbolAddress((void**)&Kp, g_K);
    cudaGetSymbolAddress((void**)&Vp, g_V);
    cudaGetSymbolAddress((void**)&Op, g_O);

    dim3 gg(DMODEL / BN, MROWS / BM);   // (8, 32)
    gemm_nt<<<gg, 256>>>(x, Wq, Qp, MROWS, DMODEL, DMODEL);
    gemm_nt<<<gg, 256>>>(x, Wk, Kp, MROWS, DMODEL, DMODEL);
    gemm_nt<<<gg, 256>>>(x, Wv, Vp, MROWS, DMODEL, DMODEL);

    rope_tables<<<(SEQ * 32 + 255) / 256, 256>>>(tp);
    int ropeN = BATCH * SEQ * (DMODEL / 2);
    rope_apply<<<(ropeN + 255) / 256, 256>>>((float2*)Qp, (float2*)Kp);

    attn_kernel<<<dim3(SEQ / 64, NHEADS, BATCH), 64>>>(Qp, Kp, Vp, Op);

    gemm_nt<<<gg, 256>>>(Op, Wo, out, MROWS, DMODEL, DMODEL);
}